// round 15
// baseline (speedup 1.0000x reference)
#include <cuda_runtime.h>
#include <math.h>
#include <cfloat>
#include <stdint.h>

#define T_TOK 2048
#define HID   2048
#define NE_OLD 128
#define NE     48
#define TOPK   8
#define INTER  768
#define CAPCT  768

// ---------------- scratch (device globals; no allocation allowed) ----------
__device__ float d_logits[T_TOK * NE_OLD];
__device__ int   d_counts[NE];
__device__ int   d_slot_token[NE * CAPCT];
__device__ int   d_sel_idx[T_TOK * TOPK];
__device__ float d_sel_w[T_TOK * TOPK];
__device__ float d_hbuf[(size_t)NE * CAPCT * INTER];   // 113 MB
__device__ float d_ybuf[(size_t)NE * CAPCT * HID];     // 302 MB

// ======================= helpers (plain sm_103-legal) ======================
__device__ __forceinline__ uint32_t f2tf32(float f) {
    uint32_t r;
    asm("cvt.rna.tf32.f32 %0, %1;" : "=r"(r) : "f"(f));
    return r;
}
__device__ __forceinline__ void mma_tf32(float* c, const uint32_t* a, const uint32_t* b) {
    asm volatile(
        "mma.sync.aligned.m16n8k8.row.col.f32.tf32.tf32.f32 "
        "{%0,%1,%2,%3}, {%4,%5,%6,%7}, {%8,%9}, {%0,%1,%2,%3};"
        : "+f"(c[0]), "+f"(c[1]), "+f"(c[2]), "+f"(c[3])
        : "r"(a[0]), "r"(a[1]), "r"(a[2]), "r"(a[3]), "r"(b[0]), "r"(b[1]));
}
__device__ __forceinline__ uint32_t smem_u32(const void* p) {
    uint32_t a;
    asm("{ .reg .u64 t; cvta.to.shared.u64 t, %1; cvt.u32.u64 %0, t; }" : "=r"(a) : "l"(p));
    return a;
}
__device__ __forceinline__ void cp16(uint32_t s, const void* g) {
    asm volatile("cp.async.ca.shared.global [%0], [%1], 16;" :: "r"(s), "l"(g));
}
#define CP_COMMIT() asm volatile("cp.async.commit_group;" ::: "memory")
#define CP_WAIT0()  asm volatile("cp.async.wait_group 0;" ::: "memory")

#define KC 32                     // K chunk per stage
#define SPAD 36                   // 32 + 4 pad floats: frag LDS conflict-free
#define TSTA (128 * SPAD * 4)     // A stage bytes (18432)
#define TSTB (256 * SPAD * 4)     // B stage bytes (36864)
#define BBASE (2 * TSTA)          // B region base
#define SMEM_BYTES (2 * TSTA + 2 * TSTB)   // 110592

// Fragment set for a 64x64 warp tile at one kk step.
struct Frags {
    uint32_t a[4][4];
    uint32_t b[8][2];
};

__device__ __forceinline__ void load_frags(const float* __restrict__ Asb,
                                           const float* __restrict__ Bsb,
                                           int kb, int wm, int wn, int g, int q,
                                           Frags& f)
{
#pragma unroll
    for (int mf = 0; mf < 4; mf++) {
        int r = wm * 64 + mf * 16;
        f.a[mf][0] = f2tf32(Asb[(r + g    ) * SPAD + kb + q    ]);
        f.a[mf][1] = f2tf32(Asb[(r + g + 8) * SPAD + kb + q    ]);
        f.a[mf][2] = f2tf32(Asb[(r + g    ) * SPAD + kb + q + 4]);
        f.a[mf][3] = f2tf32(Asb[(r + g + 8) * SPAD + kb + q + 4]);
    }
#pragma unroll
    for (int nf = 0; nf < 8; nf++) {
        int r = wn * 64 + nf * 8 + g;
        f.b[nf][0] = f2tf32(Bsb[r * SPAD + kb + q    ]);
        f.b[nf][1] = f2tf32(Bsb[r * SPAD + kb + q + 4]);
    }
}

__device__ __forceinline__ void mma_frags(float (&acc)[4][8][4], const Frags& f)
{
#pragma unroll
    for (int mf = 0; mf < 4; mf++)
#pragma unroll
        for (int nf = 0; nf < 8; nf++)
            mma_tf32(acc[mf][nf], f.a[mf], f.b[nf]);
}

// Chunk compute: software-pipelined over 4 kk steps (load kk+1 during mma kk).
__device__ __forceinline__ void chunk_compute(const float* __restrict__ Asb,
                                              const float* __restrict__ Bsb,
                                              int wm, int wn, int g, int q,
                                              float (&acc)[4][8][4])
{
    Frags f0, f1;
    load_frags(Asb, Bsb, 0, wm, wn, g, q, f0);
    load_frags(Asb, Bsb, 8, wm, wn, g, q, f1);
    mma_frags(acc, f0);
    load_frags(Asb, Bsb, 16, wm, wn, g, q, f0);
    mma_frags(acc, f1);
    load_frags(Asb, Bsb, 24, wm, wn, g, q, f1);
    mma_frags(acc, f0);
    mma_frags(acc, f1);
}

// ---------------- 1) gating logits (fp32 exact — selection must be stable) -
__global__ void __launch_bounds__(256) gating_kernel(const float* __restrict__ x,
                                                     const float* __restrict__ gw)
{
    __shared__ float Xs[32][33];
    __shared__ float Gs[32][33];
    int tid = threadIdx.x;
    if (blockIdx.x == 0 && blockIdx.y == 0 && tid < NE) d_counts[tid] = 0;

    int t0 = blockIdx.x * 32;
    int e0 = blockIdx.y * 32;
    int ty = tid / 16, tx = tid % 16;
    int lr = tid >> 3;
    int lk = (tid & 7) * 4;

    float acc00 = 0.f, acc01 = 0.f, acc10 = 0.f, acc11 = 0.f;

    for (int k0 = 0; k0 < HID; k0 += 32) {
        float4 xv = *(const float4*)&x[(size_t)(t0 + lr) * HID + k0 + lk];
        float4 gv = *(const float4*)&gw[(size_t)(e0 + lr) * HID + k0 + lk];
        __syncthreads();
        Xs[lk + 0][lr] = xv.x; Xs[lk + 1][lr] = xv.y; Xs[lk + 2][lr] = xv.z; Xs[lk + 3][lr] = xv.w;
        Gs[lk + 0][lr] = gv.x; Gs[lk + 1][lr] = gv.y; Gs[lk + 2][lr] = gv.z; Gs[lk + 3][lr] = gv.w;
        __syncthreads();
#pragma unroll
        for (int k = 0; k < 32; k++) {
            float a0 = Xs[k][ty * 2], a1 = Xs[k][ty * 2 + 1];
            float b0 = Gs[k][tx * 2], b1 = Gs[k][tx * 2 + 1];
            acc00 += a0 * b0; acc01 += a0 * b1;
            acc10 += a1 * b0; acc11 += a1 * b1;
        }
    }
    int t = t0 + ty * 2, e = e0 + tx * 2;
    d_logits[(size_t)(t + 0) * NE_OLD + e + 0] = acc00;
    d_logits[(size_t)(t + 0) * NE_OLD + e + 1] = acc01;
    d_logits[(size_t)(t + 1) * NE_OLD + e + 0] = acc10;
    d_logits[(size_t)(t + 1) * NE_OLD + e + 1] = acc11;
}

// ---------------- 2) routing ----------------------------------------------
__global__ void __launch_bounds__(256) routing_kernel(const int* __restrict__ o2n)
{
    int warp = threadIdx.x >> 5;
    int lane = threadIdx.x & 31;
    int token = blockIdx.x * 8 + warp;

    float v[4];
#pragma unroll
    for (int j = 0; j < 4; j++) {
        int ee = lane + j * 32;
        float lv = d_logits[(size_t)token * NE_OLD + ee];
        v[j] = (o2n[ee] >= 0) ? lv : -FLT_MAX;
    }

    float topv[TOPK];
    int   tope[TOPK];
#pragma unroll
    for (int it = 0; it < TOPK; it++) {
        float bv = v[0]; int be = lane;
#pragma unroll
        for (int j = 1; j < 4; j++) {
            int ee = lane + j * 32;
            if (v[j] > bv || (v[j] == bv && ee < be)) { bv = v[j]; be = ee; }
        }
#pragma unroll
        for (int off = 16; off; off >>= 1) {
            float ov = __shfl_xor_sync(0xffffffffu, bv, off);
            int   oe = __shfl_xor_sync(0xffffffffu, be, off);
            if (ov > bv || (ov == bv && oe < be)) { bv = ov; be = oe; }
        }
        topv[it] = bv; tope[it] = be;
        int wj = be >> 5;
#pragma unroll
        for (int j = 0; j < 4; j++)
            if (wj == j && (be & 31) == lane) v[j] = -FLT_MAX;
    }

    float m = topv[0];
    float w[TOPK];
    float s = 0.f;
#pragma unroll
    for (int i = 0; i < TOPK; i++) { w[i] = expf(topv[i] - m); s += w[i]; }
    float inv = 1.f / s;

    if (lane < TOPK) {
        int i = lane;
        float wi = 0.f;
        int enew = 0;
#pragma unroll
        for (int j = 0; j < TOPK; j++) if (j == i) { wi = w[j] * inv; enew = o2n[tope[j]]; }
        int pos = atomicAdd(&d_counts[enew], 1);
        int sidx = 0; float sw = 0.f;
        if (pos < CAPCT) {
            d_slot_token[enew * CAPCT + pos] = token;
            sidx = enew * CAPCT + pos;
            sw = wi;
        }
        d_sel_idx[token * TOPK + i] = sidx;
        d_sel_w[token * TOPK + i] = sw;
    }
}

// ---------------- 3) GEMM1 (tf32 mma.sync, 64x64 warp tiles) + SiLU --------
// Block: M=128 x 256 concat cols (gate 128 ++ up 128, 32-col interleave).
// 8 warps 2(M) x 4(N); warp tile 64x64. Warp wn: nf 0-3 gate, nf 4-7 up.
__global__ void __launch_bounds__(256) gemm1_mma(const float* __restrict__ x,
                                                 const float* __restrict__ gup)
{
    extern __shared__ char smem[];
    __shared__ int toks[128];
    const uint32_t sb = smem_u32(smem);

    int e = blockIdx.z;
    int cnt = min(d_counts[e], CAPCT);
    int m0 = blockIdx.y * 128;
    if (m0 >= cnt) return;
    int n0 = blockIdx.x * 128;          // gate-col base (up cols mirror at +768)
    int tid = threadIdx.x;
    int wid = tid >> 5, lane = tid & 31;
    int wm = wid >> 2, wn = wid & 3;
    int g = lane >> 2, q = lane & 3;

    if (tid < 128) {
        int m = m0 + tid;
        toks[tid] = d_slot_token[e * CAPCT + ((m < cnt) ? m : 0)];
    }
    __syncthreads();

    // loaders: A 4 float4/thread (128 rows), B 8 float4/thread (256 rows)
    const float* asrc[4]; uint32_t sA[4];
    const float* bsrc[8]; uint32_t sB[8];
#pragma unroll
    for (int j = 0; j < 4; j++) {
        int idx = tid + j * 256;
        int r = idx >> 3, qf = (idx & 7) * 4;
        sA[j] = sb + (uint32_t)(r * SPAD + qf) * 4u;
        asrc[j] = x + (size_t)toks[r] * HID + qf;
    }
#pragma unroll
    for (int j = 0; j < 8; j++) {
        int idx = tid + j * 256;
        int r = idx >> 3, qf = (idx & 7) * 4;
        sB[j] = sb + BBASE + (uint32_t)(r * SPAD + qf) * 4u;
        int w = r >> 6, l = r & 63;
        int grow = (l < 32) ? (n0 + 32 * w + l) : (768 + n0 + 32 * w + (l - 32));
        bsrc[j] = gup + (size_t)e * 1536 * HID + (size_t)grow * HID + qf;
    }

    float acc[4][8][4];
#pragma unroll
    for (int i = 0; i < 4; i++)
#pragma unroll
        for (int jn = 0; jn < 8; jn++)
#pragma unroll
            for (int c = 0; c < 4; c++) acc[i][jn][c] = 0.f;

    const int NCH = HID / KC;   // 64
#pragma unroll
    for (int j = 0; j < 4; j++) cp16(sA[j], asrc[j]);
#pragma unroll
    for (int j = 0; j < 8; j++) cp16(sB[j], bsrc[j]);
    CP_COMMIT();

    for (int i = 0; i < NCH; i++) {
        int buf = i & 1;
        CP_WAIT0();
        __syncthreads();
        if (i + 1 < NCH) {
            int nb = buf ^ 1;
            int k1 = (i + 1) * KC;
#pragma unroll
            for (int j = 0; j < 4; j++) cp16(sA[j] + nb * TSTA, asrc[j] + k1);
#pragma unroll
            for (int j = 0; j < 8; j++) cp16(sB[j] + nb * TSTB, bsrc[j] + k1);
            CP_COMMIT();
        }
        const float* Asb = (const float*)(smem + buf * TSTA);
        const float* Bsb = (const float*)(smem + BBASE + buf * TSTB);
        chunk_compute(Asb, Bsb, wm, wn, g, q, acc);
    }

    // epilogue: nf 0-3 gate, nf+4 matching up. SiLU in regs.
#pragma unroll
    for (int mf = 0; mf < 4; mf++) {
#pragma unroll
        for (int nf = 0; nf < 4; nf++) {
#pragma unroll
            for (int half = 0; half < 2; half++) {
                int m = m0 + wm * 64 + mf * 16 + g + half * 8;
                if (m < cnt) {
                    float g0 = acc[mf][nf][half * 2 + 0];
                    float g1 = acc[mf][nf][half * 2 + 1];
                    float u0 = acc[mf][nf + 4][half * 2 + 0];
                    float u1 = acc[mf][nf + 4][half * 2 + 1];
                    float2 h;
                    h.x = g0 / (1.f + __expf(-g0)) * u0;
                    h.y = g1 / (1.f + __expf(-g1)) * u1;
                    int col = n0 + 32 * wn + 8 * nf + 2 * q;
                    *(float2*)&d_hbuf[((size_t)e * CAPCT + m) * INTER + col] = h;
                }
            }
        }
    }
}

// ---------------- 4) GEMM2 (tf32 mma.sync, 64x64 warp tiles) ---------------
// Block: M=128 x N=256, K=768. 8 warps 2x4.
__global__ void __launch_bounds__(256) gemm2_mma(const float* __restrict__ down)
{
    extern __shared__ char smem[];
    const uint32_t sb = smem_u32(smem);

    int e = blockIdx.z;
    int cnt = min(d_counts[e], CAPCT);
    int m0 = blockIdx.y * 128;
    if (m0 >= cnt) return;
    int n0 = blockIdx.x * 256;
    int tid = threadIdx.x;
    int wid = tid >> 5, lane = tid & 31;
    int wm = wid >> 2, wn = wid & 3;
    int g = lane >> 2, q = lane & 3;

    const float* asrc[4]; uint32_t sA[4];
    const float* bsrc[8]; uint32_t sB[8];
#pragma unroll
    for (int j = 0; j < 4; j++) {
        int idx = tid + j * 256;
        int r = idx >> 3, qf = (idx & 7) * 4;
        sA[j] = sb + (uint32_t)(r * SPAD + qf) * 4u;
        asrc[j] = d_hbuf + ((size_t)e * CAPCT + m0 + r) * INTER + qf;
    }
#pragma unroll
    for (int j = 0; j < 8; j++) {
        int idx = tid + j * 256;
        int r = idx >> 3, qf = (idx & 7) * 4;
        sB[j] = sb + BBASE + (uint32_t)(r * SPAD + qf) * 4u;
        bsrc[j] = down + (size_t)e * HID * INTER + (size_t)(n0 + r) * INTER + qf;
    }

    float acc[4][8][4];
#pragma unroll
    for (int i = 0; i < 4; i++)
#pragma unroll
        for (int jn = 0; jn < 8; jn++)
#pragma unroll
            for (int c = 0; c < 4; c++) acc[i][jn][c] = 0.f;

    const int NCH = INTER / KC;  // 24
#pragma unroll
    for (int j = 0; j < 4; j++) cp16(sA[j], asrc[j]);
#pragma unroll
    for (int j = 0; j < 8; j++) cp16(sB[j], bsrc[j]);
    CP_COMMIT();

    for (int i = 0; i < NCH; i++) {
        int buf = i & 1;
        CP_WAIT0();
        __syncthreads();
        if (i + 1 < NCH) {
            int nb = buf ^ 1;
            int k1 = (i + 1) * KC;
#pragma unroll
            for (int j = 0; j < 4; j++) cp16(sA[j] + nb * TSTA, asrc[j] + k1);
#pragma unroll
            for (int j = 0; j < 8; j++) cp16(sB[j] + nb * TSTB, bsrc[j] + k1);
            CP_COMMIT();
        }
        const float* Asb = (const float*)(smem + buf * TSTA);
        const float* Bsb = (const float*)(smem + BBASE + buf * TSTB);
        chunk_compute(Asb, Bsb, wm, wn, g, q, acc);
    }

#pragma unroll
    for (int mf = 0; mf < 4; mf++) {
#pragma unroll
        for (int nf = 0; nf < 8; nf++) {
#pragma unroll
            for (int half = 0; half < 2; half++) {
                int m = m0 + wm * 64 + mf * 16 + g + half * 8;
                if (m < cnt) {
                    float2 yv;
                    yv.x = acc[mf][nf][half * 2 + 0];
                    yv.y = acc[mf][nf][half * 2 + 1];
                    int col = n0 + 64 * wn + 8 * nf + 2 * q;
                    *(float2*)&d_ybuf[((size_t)e * CAPCT + m) * HID + col] = yv;
                }
            }
        }
    }
}

// ---------------- 5) combine ----------------------------------------------
__global__ void __launch_bounds__(256) gather_kernel(float* __restrict__ out)
{
    int t = blockIdx.x;
    __shared__ int  sidx[TOPK];
    __shared__ float sw[TOPK];
    if (threadIdx.x < TOPK) {
        sidx[threadIdx.x] = d_sel_idx[t * TOPK + threadIdx.x];
        sw[threadIdx.x]   = d_sel_w[t * TOPK + threadIdx.x];
    }
    __syncthreads();

    const float4* yb = (const float4*)d_ybuf;
    float4* o = (float4*)(out + (size_t)t * HID);
#pragma unroll
    for (int v = threadIdx.x; v < HID / 4; v += 256) {
        float4 acc = {0.f, 0.f, 0.f, 0.f};
#pragma unroll
        for (int k = 0; k < TOPK; k++) {
            float4 yv = yb[(size_t)sidx[k] * (HID / 4) + v];
            float wk = sw[k];
            acc.x += wk * yv.x; acc.y += wk * yv.y;
            acc.z += wk * yv.z; acc.w += wk * yv.w;
        }
        o[v] = acc;
    }
}

// ---------------- launch ---------------------------------------------------
extern "C" void kernel_launch(void* const* d_in, const int* in_sizes, int n_in,
                              void* d_out, int out_size)
{
    const float* x    = (const float*)d_in[0];   // hidden_states [2,1024,2048]
    const float* gw   = (const float*)d_in[1];   // gate_weight [128,2048]
    const float* gup  = (const float*)d_in[2];   // gate_up_proj [48,1536,2048]
    const float* down = (const float*)d_in[3];   // down_proj [48,2048,768]
    const int*   o2n  = (const int*)d_in[4];     // old_to_new [128]

    cudaFuncSetAttribute(gemm1_mma, cudaFuncAttributeMaxDynamicSharedMemorySize, SMEM_BYTES);
    cudaFuncSetAttribute(gemm2_mma, cudaFuncAttributeMaxDynamicSharedMemorySize, SMEM_BYTES);

    gating_kernel<<<dim3(T_TOK / 32, NE_OLD / 32), 256>>>(x, gw);
    routing_kernel<<<T_TOK / 8, 256>>>(o2n);
    gemm1_mma<<<dim3(INTER / 128, CAPCT / 128, NE), 256, SMEM_BYTES>>>(x, gup);
    gemm2_mma<<<dim3(HID / 256, CAPCT / 128, NE), 256, SMEM_BYTES>>>(down);
    gather_kernel<<<T_TOK, 256>>>((float*)d_out);
}

// round 16
// speedup vs baseline: 1.3025x; 1.3025x over previous
#include <cuda_runtime.h>
#include <math.h>
#include <cfloat>
#include <stdint.h>

#define T_TOK 2048
#define HID   2048
#define NE_OLD 128
#define NE     48
#define TOPK   8
#define INTER  768
#define CAPCT  768

// ---------------- scratch (device globals; no allocation allowed) ----------
__device__ float d_logits[T_TOK * NE_OLD];
__device__ int   d_counts[NE];
__device__ int   d_slot_token[NE * CAPCT];
__device__ int   d_sel_idx[T_TOK * TOPK];
__device__ float d_sel_w[T_TOK * TOPK];
__device__ float d_hbuf[(size_t)NE * CAPCT * INTER];   // 113 MB
__device__ float d_ybuf[(size_t)NE * CAPCT * HID];     // 302 MB

// ======================= helpers (plain sm_103-legal) ======================
// pack two f32 -> f16x2 (lo = first k, hi = second k)
__device__ __forceinline__ uint32_t pack_h2(float lo, float hi) {
    uint32_t r;
    asm("cvt.rn.f16x2.f32 %0, %1, %2;" : "=r"(r) : "f"(hi), "f"(lo));
    return r;
}
__device__ __forceinline__ void mma_f16(float* c, const uint32_t* a, const uint32_t* b) {
    asm volatile(
        "mma.sync.aligned.m16n8k16.row.col.f32.f16.f16.f32 "
        "{%0,%1,%2,%3}, {%4,%5,%6,%7}, {%8,%9}, {%0,%1,%2,%3};"
        : "+f"(c[0]), "+f"(c[1]), "+f"(c[2]), "+f"(c[3])
        : "r"(a[0]), "r"(a[1]), "r"(a[2]), "r"(a[3]), "r"(b[0]), "r"(b[1]));
}
__device__ __forceinline__ uint32_t smem_u32(const void* p) {
    uint32_t a;
    asm("{ .reg .u64 t; cvta.to.shared.u64 t, %1; cvt.u32.u64 %0, t; }" : "=r"(a) : "l"(p));
    return a;
}
__device__ __forceinline__ void cp16(uint32_t s, const void* g) {
    asm volatile("cp.async.ca.shared.global [%0], [%1], 16;" :: "r"(s), "l"(g));
}
#define CP_COMMIT() asm volatile("cp.async.commit_group;" ::: "memory")
#define CP_WAIT0()  asm volatile("cp.async.wait_group 0;" ::: "memory")

#define KC 32                     // K chunk per stage (2 x k16 mma steps)
#define SPAD 40                   // row stride floats: LDS.64 conflict-free, 16B-mult
#define TSTA (128 * SPAD * 4)     // A stage bytes (20480)
#define TSTB (256 * SPAD * 4)     // B stage bytes (40960)
#define BBASE (2 * TSTA)          // B region base
#define SMEM_BYTES (2 * TSTA + 2 * TSTB)   // 122880

// Fragment set for a 64x64 warp tile at one k16 step (fp16 operands).
struct Frags {
    uint32_t a[4][4];
    uint32_t b[8][2];
};

// Load + convert fragments for k16 step at column kb (0 or 16).
// m16n8k16 layout: a0=(row g, k 2q..2q+1), a1=(row g+8, same), a2/a3 = +8 k.
__device__ __forceinline__ void load_frags(const float* __restrict__ Asb,
                                           const float* __restrict__ Bsb,
                                           int kb, int wm, int wn, int g, int q,
                                           Frags& f)
{
#pragma unroll
    for (int mf = 0; mf < 4; mf++) {
        int r = wm * 64 + mf * 16;
        float2 v0 = *(const float2*)&Asb[(r + g    ) * SPAD + kb + 2 * q];
        float2 v1 = *(const float2*)&Asb[(r + g + 8) * SPAD + kb + 2 * q];
        float2 v2 = *(const float2*)&Asb[(r + g    ) * SPAD + kb + 8 + 2 * q];
        float2 v3 = *(const float2*)&Asb[(r + g + 8) * SPAD + kb + 8 + 2 * q];
        f.a[mf][0] = pack_h2(v0.x, v0.y);
        f.a[mf][1] = pack_h2(v1.x, v1.y);
        f.a[mf][2] = pack_h2(v2.x, v2.y);
        f.a[mf][3] = pack_h2(v3.x, v3.y);
    }
#pragma unroll
    for (int nf = 0; nf < 8; nf++) {
        int r = wn * 64 + nf * 8 + g;
        float2 v0 = *(const float2*)&Bsb[r * SPAD + kb + 2 * q];
        float2 v1 = *(const float2*)&Bsb[r * SPAD + kb + 8 + 2 * q];
        f.b[nf][0] = pack_h2(v0.x, v0.y);
        f.b[nf][1] = pack_h2(v1.x, v1.y);
    }
}

__device__ __forceinline__ void mma_frags(float (&acc)[4][8][4], const Frags& f)
{
#pragma unroll
    for (int mf = 0; mf < 4; mf++)
#pragma unroll
        for (int nf = 0; nf < 8; nf++)
            mma_f16(acc[mf][nf], f.a[mf], f.b[nf]);
}

// Chunk compute: 2 k16 steps.
__device__ __forceinline__ void chunk_compute(const float* __restrict__ Asb,
                                              const float* __restrict__ Bsb,
                                              int wm, int wn, int g, int q,
                                              float (&acc)[4][8][4])
{
    Frags f0, f1;
    load_frags(Asb, Bsb, 0, wm, wn, g, q, f0);
    load_frags(Asb, Bsb, 16, wm, wn, g, q, f1);
    mma_frags(acc, f0);
    mma_frags(acc, f1);
}

// ---------------- 1) gating logits (fp32 exact — selection must be stable) -
__global__ void __launch_bounds__(256) gating_kernel(const float* __restrict__ x,
                                                     const float* __restrict__ gw)
{
    __shared__ float Xs[32][33];
    __shared__ float Gs[32][33];
    int tid = threadIdx.x;
    if (blockIdx.x == 0 && blockIdx.y == 0 && tid < NE) d_counts[tid] = 0;

    int t0 = blockIdx.x * 32;
    int e0 = blockIdx.y * 32;
    int ty = tid / 16, tx = tid % 16;
    int lr = tid >> 3;
    int lk = (tid & 7) * 4;

    float acc00 = 0.f, acc01 = 0.f, acc10 = 0.f, acc11 = 0.f;

    for (int k0 = 0; k0 < HID; k0 += 32) {
        float4 xv = *(const float4*)&x[(size_t)(t0 + lr) * HID + k0 + lk];
        float4 gv = *(const float4*)&gw[(size_t)(e0 + lr) * HID + k0 + lk];
        __syncthreads();
        Xs[lk + 0][lr] = xv.x; Xs[lk + 1][lr] = xv.y; Xs[lk + 2][lr] = xv.z; Xs[lk + 3][lr] = xv.w;
        Gs[lk + 0][lr] = gv.x; Gs[lk + 1][lr] = gv.y; Gs[lk + 2][lr] = gv.z; Gs[lk + 3][lr] = gv.w;
        __syncthreads();
#pragma unroll
        for (int k = 0; k < 32; k++) {
            float a0 = Xs[k][ty * 2], a1 = Xs[k][ty * 2 + 1];
            float b0 = Gs[k][tx * 2], b1 = Gs[k][tx * 2 + 1];
            acc00 += a0 * b0; acc01 += a0 * b1;
            acc10 += a1 * b0; acc11 += a1 * b1;
        }
    }
    int t = t0 + ty * 2, e = e0 + tx * 2;
    d_logits[(size_t)(t + 0) * NE_OLD + e + 0] = acc00;
    d_logits[(size_t)(t + 0) * NE_OLD + e + 1] = acc01;
    d_logits[(size_t)(t + 1) * NE_OLD + e + 0] = acc10;
    d_logits[(size_t)(t + 1) * NE_OLD + e + 1] = acc11;
}

// ---------------- 2) routing ----------------------------------------------
__global__ void __launch_bounds__(256) routing_kernel(const int* __restrict__ o2n)
{
    int warp = threadIdx.x >> 5;
    int lane = threadIdx.x & 31;
    int token = blockIdx.x * 8 + warp;

    float v[4];
#pragma unroll
    for (int j = 0; j < 4; j++) {
        int ee = lane + j * 32;
        float lv = d_logits[(size_t)token * NE_OLD + ee];
        v[j] = (o2n[ee] >= 0) ? lv : -FLT_MAX;
    }

    float topv[TOPK];
    int   tope[TOPK];
#pragma unroll
    for (int it = 0; it < TOPK; it++) {
        float bv = v[0]; int be = lane;
#pragma unroll
        for (int j = 1; j < 4; j++) {
            int ee = lane + j * 32;
            if (v[j] > bv || (v[j] == bv && ee < be)) { bv = v[j]; be = ee; }
        }
#pragma unroll
        for (int off = 16; off; off >>= 1) {
            float ov = __shfl_xor_sync(0xffffffffu, bv, off);
            int   oe = __shfl_xor_sync(0xffffffffu, be, off);
            if (ov > bv || (ov == bv && oe < be)) { bv = ov; be = oe; }
        }
        topv[it] = bv; tope[it] = be;
        int wj = be >> 5;
#pragma unroll
        for (int j = 0; j < 4; j++)
            if (wj == j && (be & 31) == lane) v[j] = -FLT_MAX;
    }

    float m = topv[0];
    float w[TOPK];
    float s = 0.f;
#pragma unroll
    for (int i = 0; i < TOPK; i++) { w[i] = expf(topv[i] - m); s += w[i]; }
    float inv = 1.f / s;

    if (lane < TOPK) {
        int i = lane;
        float wi = 0.f;
        int enew = 0;
#pragma unroll
        for (int j = 0; j < TOPK; j++) if (j == i) { wi = w[j] * inv; enew = o2n[tope[j]]; }
        int pos = atomicAdd(&d_counts[enew], 1);
        int sidx = 0; float sw = 0.f;
        if (pos < CAPCT) {
            d_slot_token[enew * CAPCT + pos] = token;
            sidx = enew * CAPCT + pos;
            sw = wi;
        }
        d_sel_idx[token * TOPK + i] = sidx;
        d_sel_w[token * TOPK + i] = sw;
    }
}

// ---------------- 3) GEMM1 (fp16 mma.sync, 64x64 warp tiles) + SiLU --------
// Block: M=128 x 256 concat cols (gate 128 ++ up 128, 32-col interleave).
// 8 warps 2(M) x 4(N); warp tile 64x64. Warp wn: nf 0-3 gate, nf 4-7 up.
__global__ void __launch_bounds__(256) gemm1_mma(const float* __restrict__ x,
                                                 const float* __restrict__ gup)
{
    extern __shared__ char smem[];
    __shared__ int toks[128];
    const uint32_t sb = smem_u32(smem);

    int e = blockIdx.z;
    int cnt = min(d_counts[e], CAPCT);
    int m0 = blockIdx.y * 128;
    if (m0 >= cnt) return;
    int n0 = blockIdx.x * 128;          // gate-col base (up cols mirror at +768)
    int tid = threadIdx.x;
    int wid = tid >> 5, lane = tid & 31;
    int wm = wid >> 2, wn = wid & 3;
    int g = lane >> 2, q = lane & 3;

    if (tid < 128) {
        int m = m0 + tid;
        toks[tid] = d_slot_token[e * CAPCT + ((m < cnt) ? m : 0)];
    }
    __syncthreads();

    // loaders: A 4 float4/thread (128 rows), B 8 float4/thread (256 rows)
    const float* asrc[4]; uint32_t sA[4];
    const float* bsrc[8]; uint32_t sB[8];
#pragma unroll
    for (int j = 0; j < 4; j++) {
        int idx = tid + j * 256;
        int r = idx >> 3, qf = (idx & 7) * 4;
        sA[j] = sb + (uint32_t)(r * SPAD + qf) * 4u;
        asrc[j] = x + (size_t)toks[r] * HID + qf;
    }
#pragma unroll
    for (int j = 0; j < 8; j++) {
        int idx = tid + j * 256;
        int r = idx >> 3, qf = (idx & 7) * 4;
        sB[j] = sb + BBASE + (uint32_t)(r * SPAD + qf) * 4u;
        int w = r >> 6, l = r & 63;
        int grow = (l < 32) ? (n0 + 32 * w + l) : (768 + n0 + 32 * w + (l - 32));
        bsrc[j] = gup + (size_t)e * 1536 * HID + (size_t)grow * HID + qf;
    }

    float acc[4][8][4];
#pragma unroll
    for (int i = 0; i < 4; i++)
#pragma unroll
        for (int jn = 0; jn < 8; jn++)
#pragma unroll
            for (int c = 0; c < 4; c++) acc[i][jn][c] = 0.f;

    const int NCH = HID / KC;   // 64
#pragma unroll
    for (int j = 0; j < 4; j++) cp16(sA[j], asrc[j]);
#pragma unroll
    for (int j = 0; j < 8; j++) cp16(sB[j], bsrc[j]);
    CP_COMMIT();

    for (int i = 0; i < NCH; i++) {
        int buf = i & 1;
        CP_WAIT0();
        __syncthreads();
        if (i + 1 < NCH) {
            int nb = buf ^ 1;
            int k1 = (i + 1) * KC;
#pragma unroll
            for (int j = 0; j < 4; j++) cp16(sA[j] + nb * TSTA, asrc[j] + k1);
#pragma unroll
            for (int j = 0; j < 8; j++) cp16(sB[j] + nb * TSTB, bsrc[j] + k1);
            CP_COMMIT();
        }
        const float* Asb = (const float*)(smem + buf * TSTA);
        const float* Bsb = (const float*)(smem + BBASE + buf * TSTB);
        chunk_compute(Asb, Bsb, wm, wn, g, q, acc);
    }

    // epilogue: nf 0-3 gate, nf+4 matching up. SiLU in regs.
#pragma unroll
    for (int mf = 0; mf < 4; mf++) {
#pragma unroll
        for (int nf = 0; nf < 4; nf++) {
#pragma unroll
            for (int half = 0; half < 2; half++) {
                int m = m0 + wm * 64 + mf * 16 + g + half * 8;
                if (m < cnt) {
                    float g0 = acc[mf][nf][half * 2 + 0];
                    float g1 = acc[mf][nf][half * 2 + 1];
                    float u0 = acc[mf][nf + 4][half * 2 + 0];
                    float u1 = acc[mf][nf + 4][half * 2 + 1];
                    float2 h;
                    h.x = g0 / (1.f + __expf(-g0)) * u0;
                    h.y = g1 / (1.f + __expf(-g1)) * u1;
                    int col = n0 + 32 * wn + 8 * nf + 2 * q;
                    *(float2*)&d_hbuf[((size_t)e * CAPCT + m) * INTER + col] = h;
                }
            }
        }
    }
}

// ---------------- 4) GEMM2 (fp16 mma.sync, 64x64 warp tiles) ---------------
// Block: M=128 x N=256, K=768. 8 warps 2x4.
__global__ void __launch_bounds__(256) gemm2_mma(const float* __restrict__ down)
{
    extern __shared__ char smem[];
    const uint32_t sb = smem_u32(smem);

    int e = blockIdx.z;
    int cnt = min(d_counts[e], CAPCT);
    int m0 = blockIdx.y * 128;
    if (m0 >= cnt) return;
    int n0 = blockIdx.x * 256;
    int tid = threadIdx.x;
    int wid = tid >> 5, lane = tid & 31;
    int wm = wid >> 2, wn = wid & 3;
    int g = lane >> 2, q = lane & 3;

    const float* asrc[4]; uint32_t sA[4];
    const float* bsrc[8]; uint32_t sB[8];
#pragma unroll
    for (int j = 0; j < 4; j++) {
        int idx = tid + j * 256;
        int r = idx >> 3, qf = (idx & 7) * 4;
        sA[j] = sb + (uint32_t)(r * SPAD + qf) * 4u;
        asrc[j] = d_hbuf + ((size_t)e * CAPCT + m0 + r) * INTER + qf;
    }
#pragma unroll
    for (int j = 0; j < 8; j++) {
        int idx = tid + j * 256;
        int r = idx >> 3, qf = (idx & 7) * 4;
        sB[j] = sb + BBASE + (uint32_t)(r * SPAD + qf) * 4u;
        bsrc[j] = down + (size_t)e * HID * INTER + (size_t)(n0 + r) * INTER + qf;
    }

    float acc[4][8][4];
#pragma unroll
    for (int i = 0; i < 4; i++)
#pragma unroll
        for (int jn = 0; jn < 8; jn++)
#pragma unroll
            for (int c = 0; c < 4; c++) acc[i][jn][c] = 0.f;

    const int NCH = INTER / KC;  // 24
#pragma unroll
    for (int j = 0; j < 4; j++) cp16(sA[j], asrc[j]);
#pragma unroll
    for (int j = 0; j < 8; j++) cp16(sB[j], bsrc[j]);
    CP_COMMIT();

    for (int i = 0; i < NCH; i++) {
        int buf = i & 1;
        CP_WAIT0();
        __syncthreads();
        if (i + 1 < NCH) {
            int nb = buf ^ 1;
            int k1 = (i + 1) * KC;
#pragma unroll
            for (int j = 0; j < 4; j++) cp16(sA[j] + nb * TSTA, asrc[j] + k1);
#pragma unroll
            for (int j = 0; j < 8; j++) cp16(sB[j] + nb * TSTB, bsrc[j] + k1);
            CP_COMMIT();
        }
        const float* Asb = (const float*)(smem + buf * TSTA);
        const float* Bsb = (const float*)(smem + BBASE + buf * TSTB);
        chunk_compute(Asb, Bsb, wm, wn, g, q, acc);
    }

#pragma unroll
    for (int mf = 0; mf < 4; mf++) {
#pragma unroll
        for (int nf = 0; nf < 8; nf++) {
#pragma unroll
            for (int half = 0; half < 2; half++) {
                int m = m0 + wm * 64 + mf * 16 + g + half * 8;
                if (m < cnt) {
                    float2 yv;
                    yv.x = acc[mf][nf][half * 2 + 0];
                    yv.y = acc[mf][nf][half * 2 + 1];
                    int col = n0 + 64 * wn + 8 * nf + 2 * q;
                    *(float2*)&d_ybuf[((size_t)e * CAPCT + m) * HID + col] = yv;
                }
            }
        }
    }
}

// ---------------- 5) combine ----------------------------------------------
__global__ void __launch_bounds__(256) gather_kernel(float* __restrict__ out)
{
    int t = blockIdx.x;
    __shared__ int  sidx[TOPK];
    __shared__ float sw[TOPK];
    if (threadIdx.x < TOPK) {
        sidx[threadIdx.x] = d_sel_idx[t * TOPK + threadIdx.x];
        sw[threadIdx.x]   = d_sel_w[t * TOPK + threadIdx.x];
    }
    __syncthreads();

    const float4* yb = (const float4*)d_ybuf;
    float4* o = (float4*)(out + (size_t)t * HID);
#pragma unroll
    for (int v = threadIdx.x; v < HID / 4; v += 256) {
        float4 acc = {0.f, 0.f, 0.f, 0.f};
#pragma unroll
        for (int k = 0; k < TOPK; k++) {
            float4 yv = yb[(size_t)sidx[k] * (HID / 4) + v];
            float wk = sw[k];
            acc.x += wk * yv.x; acc.y += wk * yv.y;
            acc.z += wk * yv.z; acc.w += wk * yv.w;
        }
        o[v] = acc;
    }
}

// ---------------- launch ---------------------------------------------------
extern "C" void kernel_launch(void* const* d_in, const int* in_sizes, int n_in,
                              void* d_out, int out_size)
{
    const float* x    = (const float*)d_in[0];   // hidden_states [2,1024,2048]
    const float* gw   = (const float*)d_in[1];   // gate_weight [128,2048]
    const float* gup  = (const float*)d_in[2];   // gate_up_proj [48,1536,2048]
    const float* down = (const float*)d_in[3];   // down_proj [48,2048,768]
    const int*   o2n  = (const int*)d_in[4];     // old_to_new [128]

    cudaFuncSetAttribute(gemm1_mma, cudaFuncAttributeMaxDynamicSharedMemorySize, SMEM_BYTES);
    cudaFuncSetAttribute(gemm2_mma, cudaFuncAttributeMaxDynamicSharedMemorySize, SMEM_BYTES);

    gating_kernel<<<dim3(T_TOK / 32, NE_OLD / 32), 256>>>(x, gw);
    routing_kernel<<<T_TOK / 8, 256>>>(o2n);
    gemm1_mma<<<dim3(INTER / 128, CAPCT / 128, NE), 256, SMEM_BYTES>>>(x, gup);
    gemm2_mma<<<dim3(HID / 256, CAPCT / 128, NE), 256, SMEM_BYTES>>>(down);
    gather_kernel<<<T_TOK, 256>>>((float*)d_out);
}

// round 17
// speedup vs baseline: 1.5723x; 1.2071x over previous
#include <cuda_runtime.h>
#include <cuda_fp16.h>
#include <math.h>
#include <cfloat>
#include <stdint.h>

#define T_TOK 2048
#define HID   2048
#define NE_OLD 128
#define NE     48
#define TOPK   8
#define INTER  768
#define CAPCT  768

// ---------------- scratch (device globals; no allocation allowed) ----------
__device__ float d_logits[T_TOK * NE_OLD];
__device__ int   d_counts[NE];
__device__ int   d_slot_token[NE * CAPCT];
__device__ int   d_sel_idx[T_TOK * TOPK];
__device__ float d_sel_w[T_TOK * TOPK];
__device__ __half d_xh[(size_t)T_TOK * HID];                 // 8 MB fp16 activations
__device__ __half d_hbuf16[(size_t)NE * CAPCT * INTER];     // 57 MB fp16 h
__device__ float d_ybuf[(size_t)NE * CAPCT * HID];          // 302 MB

// ======================= helpers (plain sm_103-legal) ======================
__device__ __forceinline__ uint32_t pack_h2(float lo, float hi) {
    uint32_t r;
    asm("cvt.rn.f16x2.f32 %0, %1, %2;" : "=r"(r) : "f"(hi), "f"(lo));
    return r;
}
__device__ __forceinline__ void mma_f16(float* c, const uint32_t* a, const uint32_t* b) {
    asm volatile(
        "mma.sync.aligned.m16n8k16.row.col.f32.f16.f16.f32 "
        "{%0,%1,%2,%3}, {%4,%5,%6,%7}, {%8,%9}, {%0,%1,%2,%3};"
        : "+f"(c[0]), "+f"(c[1]), "+f"(c[2]), "+f"(c[3])
        : "r"(a[0]), "r"(a[1]), "r"(a[2]), "r"(a[3]), "r"(b[0]), "r"(b[1]));
}
__device__ __forceinline__ uint32_t smem_u32(const void* p) {
    uint32_t a;
    asm("{ .reg .u64 t; cvta.to.shared.u64 t, %1; cvt.u32.u64 %0, t; }" : "=r"(a) : "l"(p));
    return a;
}
__device__ __forceinline__ void cp16(uint32_t s, const void* g) {
    asm volatile("cp.async.ca.shared.global [%0], [%1], 16;" :: "r"(s), "l"(g));
}
__device__ __forceinline__ void sts8(uint32_t s, uint32_t x, uint32_t y) {
    asm volatile("st.shared.v2.u32 [%0], {%1, %2};" :: "r"(s), "r"(x), "r"(y) : "memory");
}
#define CP_COMMIT() asm volatile("cp.async.commit_group;" ::: "memory")
#define CP_WAIT0()  asm volatile("cp.async.wait_group 0;" ::: "memory")

#define KC 32                       // K chunk (halves) per stage = 2 x k16 steps
#define ASTG 10240                  // A stage: 128 rows x 80 B (40-half stride)
#define BSTG 16384                  // B stage: 256 rows x 64 B (16-word swizzled)
#define BBASE (2 * ASTG)            // 20480
#define SMEM_BYTES (BBASE + 2 * BSTG)   // 53248

// ---- fragment loads: direct fp16 LDS.32, no conversion -------------------
// A smem: row stride 20 words; word (r,kw) at r*20+kw. Conflict-free.
// B smem: row stride 16 words; word (r,kw) at r*16 + ((kw + 2r)&15). Conflict-free.
__device__ __forceinline__ void compute_chunk(const uint32_t* __restrict__ Aw,
                                              const uint32_t* __restrict__ Bw,
                                              int wm, int wn, int g, int q,
                                              float (&acc)[4][8][4])
{
#pragma unroll
    for (int kb2 = 0; kb2 < 16; kb2 += 8) {
        uint32_t a[4][4], b[8][2];
#pragma unroll
        for (int mf = 0; mf < 4; mf++) {
            int r = wm * 64 + mf * 16;
            a[mf][0] = Aw[(r + g    ) * 20 + kb2 + q];
            a[mf][1] = Aw[(r + g + 8) * 20 + kb2 + q];
            a[mf][2] = Aw[(r + g    ) * 20 + kb2 + q + 4];
            a[mf][3] = Aw[(r + g + 8) * 20 + kb2 + q + 4];
        }
#pragma unroll
        for (int nf = 0; nf < 8; nf++) {
            int r = wn * 64 + nf * 8 + g;
            b[nf][0] = Bw[r * 16 + ((kb2 + q + 2 * r) & 15)];
            b[nf][1] = Bw[r * 16 + ((kb2 + 4 + q + 2 * r) & 15)];
        }
#pragma unroll
        for (int mf = 0; mf < 4; mf++)
#pragma unroll
            for (int nf = 0; nf < 8; nf++)
                mma_f16(acc[mf][nf], a[mf], b[nf]);
    }
}

// ---------------- 0) x -> fp16 --------------------------------------------
__global__ void __launch_bounds__(256) convert_x(const float* __restrict__ x)
{
    int i = blockIdx.x * 256 + threadIdx.x;          // over float4s
    float4 v = ((const float4*)x)[i];
    uint2 p;
    p.x = pack_h2(v.x, v.y);
    p.y = pack_h2(v.z, v.w);
    ((uint2*)d_xh)[i] = p;
}

// ---------------- 1) gating logits (fp32 exact) ---------------------------
__global__ void __launch_bounds__(256) gating_kernel(const float* __restrict__ x,
                                                     const float* __restrict__ gw)
{
    __shared__ float Xs[32][33];
    __shared__ float Gs[32][33];
    int tid = threadIdx.x;
    if (blockIdx.x == 0 && blockIdx.y == 0 && tid < NE) d_counts[tid] = 0;

    int t0 = blockIdx.x * 32;
    int e0 = blockIdx.y * 32;
    int ty = tid / 16, tx = tid % 16;
    int lr = tid >> 3;
    int lk = (tid & 7) * 4;

    float acc00 = 0.f, acc01 = 0.f, acc10 = 0.f, acc11 = 0.f;

    for (int k0 = 0; k0 < HID; k0 += 32) {
        float4 xv = *(const float4*)&x[(size_t)(t0 + lr) * HID + k0 + lk];
        float4 gv = *(const float4*)&gw[(size_t)(e0 + lr) * HID + k0 + lk];
        __syncthreads();
        Xs[lk + 0][lr] = xv.x; Xs[lk + 1][lr] = xv.y; Xs[lk + 2][lr] = xv.z; Xs[lk + 3][lr] = xv.w;
        Gs[lk + 0][lr] = gv.x; Gs[lk + 1][lr] = gv.y; Gs[lk + 2][lr] = gv.z; Gs[lk + 3][lr] = gv.w;
        __syncthreads();
#pragma unroll
        for (int k = 0; k < 32; k++) {
            float a0 = Xs[k][ty * 2], a1 = Xs[k][ty * 2 + 1];
            float b0 = Gs[k][tx * 2], b1 = Gs[k][tx * 2 + 1];
            acc00 += a0 * b0; acc01 += a0 * b1;
            acc10 += a1 * b0; acc11 += a1 * b1;
        }
    }
    int t = t0 + ty * 2, e = e0 + tx * 2;
    d_logits[(size_t)(t + 0) * NE_OLD + e + 0] = acc00;
    d_logits[(size_t)(t + 0) * NE_OLD + e + 1] = acc01;
    d_logits[(size_t)(t + 1) * NE_OLD + e + 0] = acc10;
    d_logits[(size_t)(t + 1) * NE_OLD + e + 1] = acc11;
}

// ---------------- 2) routing ----------------------------------------------
__global__ void __launch_bounds__(256) routing_kernel(const int* __restrict__ o2n)
{
    int warp = threadIdx.x >> 5;
    int lane = threadIdx.x & 31;
    int token = blockIdx.x * 8 + warp;

    float v[4];
#pragma unroll
    for (int j = 0; j < 4; j++) {
        int ee = lane + j * 32;
        float lv = d_logits[(size_t)token * NE_OLD + ee];
        v[j] = (o2n[ee] >= 0) ? lv : -FLT_MAX;
    }

    float topv[TOPK];
    int   tope[TOPK];
#pragma unroll
    for (int it = 0; it < TOPK; it++) {
        float bv = v[0]; int be = lane;
#pragma unroll
        for (int j = 1; j < 4; j++) {
            int ee = lane + j * 32;
            if (v[j] > bv || (v[j] == bv && ee < be)) { bv = v[j]; be = ee; }
        }
#pragma unroll
        for (int off = 16; off; off >>= 1) {
            float ov = __shfl_xor_sync(0xffffffffu, bv, off);
            int   oe = __shfl_xor_sync(0xffffffffu, be, off);
            if (ov > bv || (ov == bv && oe < be)) { bv = ov; be = oe; }
        }
        topv[it] = bv; tope[it] = be;
        int wj = be >> 5;
#pragma unroll
        for (int j = 0; j < 4; j++)
            if (wj == j && (be & 31) == lane) v[j] = -FLT_MAX;
    }

    float m = topv[0];
    float w[TOPK];
    float s = 0.f;
#pragma unroll
    for (int i = 0; i < TOPK; i++) { w[i] = expf(topv[i] - m); s += w[i]; }
    float inv = 1.f / s;

    if (lane < TOPK) {
        int i = lane;
        float wi = 0.f;
        int enew = 0;
#pragma unroll
        for (int j = 0; j < TOPK; j++) if (j == i) { wi = w[j] * inv; enew = o2n[tope[j]]; }
        int pos = atomicAdd(&d_counts[enew], 1);
        int sidx = 0; float sw = 0.f;
        if (pos < CAPCT) {
            d_slot_token[enew * CAPCT + pos] = token;
            sidx = enew * CAPCT + pos;
            sw = wi;
        }
        d_sel_idx[token * TOPK + i] = sidx;
        d_sel_w[token * TOPK + i] = sw;
    }
}

// ---------------- 3) GEMM1 (fp16 smem both sides) + SiLU -------------------
// Block: M=128 x 256 concat cols (gate 128 ++ up 128, 32-col interleave).
// 8 warps 2x4, warp tile 64x64. A fp16 via cp.async (d_xh); B fp32 LDG ->
// pack -> swizzled fp16 STS, staged one chunk ahead in registers.
__global__ void __launch_bounds__(256) gemm1_mma(const float* __restrict__ gup)
{
    extern __shared__ char smem[];
    __shared__ int toks[128];
    const uint32_t sb = smem_u32(smem);

    int e = blockIdx.z;
    int cnt = min(d_counts[e], CAPCT);
    int m0 = blockIdx.y * 128;
    if (m0 >= cnt) return;
    int n0 = blockIdx.x * 128;          // gate-col base (up cols mirror at +768)
    int tid = threadIdx.x;
    int wid = tid >> 5, lane = tid & 31;
    int wm = wid >> 2, wn = wid & 3;
    int g = lane >> 2, q = lane & 3;

    if (tid < 128) {
        int m = m0 + tid;
        toks[tid] = d_slot_token[e * CAPCT + ((m < cnt) ? m : 0)];
    }
    __syncthreads();

    // A loader: 2 x 16B per thread (128 rows x 64 B)
    const __half* aptr[2]; uint32_t sAoff[2];
#pragma unroll
    for (int j = 0; j < 2; j++) {
        int idx = tid + j * 256;
        int r = idx >> 2, o = idx & 3;
        sAoff[j] = (uint32_t)(r * 80 + o * 16);
        aptr[j] = d_xh + (size_t)toks[r] * HID + o * 8;
    }
    // B loader: 8 float4 per thread (256 rows x 32 floats)
    const float* bsrc[8]; uint32_t bsts[8];
#pragma unroll
    for (int j = 0; j < 8; j++) {
        int idx = tid + j * 256;
        int r = idx >> 3, qf = (idx & 7) * 4;
        int kw = qf >> 1;
        bsts[j] = sb + BBASE + (uint32_t)((r * 16 + ((kw + 2 * r) & 15)) * 4);
        int w = r >> 6, l = r & 63;
        int grow = (l < 32) ? (n0 + 32 * w + l) : (768 + n0 + 32 * w + (l - 32));
        bsrc[j] = gup + (size_t)e * 1536 * HID + (size_t)grow * HID + qf;
    }

    float acc[4][8][4];
#pragma unroll
    for (int i = 0; i < 4; i++)
#pragma unroll
        for (int jn = 0; jn < 8; jn++)
#pragma unroll
            for (int c = 0; c < 4; c++) acc[i][jn][c] = 0.f;

    const int NCH = HID / KC;   // 64
    // prologue: A(0) via cp.async, B(0) into regs
#pragma unroll
    for (int j = 0; j < 2; j++) cp16(sb + sAoff[j], aptr[j]);
    CP_COMMIT();
    float4 rB[8];
#pragma unroll
    for (int j = 0; j < 8; j++) rB[j] = *(const float4*)bsrc[j];

    for (int i = 0; i < NCH; i++) {
        int buf = i & 1;
        CP_WAIT0();
#pragma unroll
        for (int j = 0; j < 8; j++)
            sts8(bsts[j] + buf * BSTG, pack_h2(rB[j].x, rB[j].y), pack_h2(rB[j].z, rB[j].w));
        __syncthreads();
        if (i + 1 < NCH) {
            int nb = buf ^ 1;
            int k1 = (i + 1) * KC;
#pragma unroll
            for (int j = 0; j < 2; j++) cp16(sb + nb * ASTG + sAoff[j], aptr[j] + k1);
            CP_COMMIT();
#pragma unroll
            for (int j = 0; j < 8; j++) rB[j] = *(const float4*)(bsrc[j] + k1);
        }
        compute_chunk((const uint32_t*)(smem + buf * ASTG),
                      (const uint32_t*)(smem + BBASE + buf * BSTG),
                      wm, wn, g, q, acc);
    }

    // epilogue: nf 0-3 gate, nf+4 matching up. SiLU in regs -> fp16 hbuf.
#pragma unroll
    for (int mf = 0; mf < 4; mf++) {
#pragma unroll
        for (int nf = 0; nf < 4; nf++) {
#pragma unroll
            for (int half = 0; half < 2; half++) {
                int m = m0 + wm * 64 + mf * 16 + g + half * 8;
                if (m < cnt) {
                    float g0 = acc[mf][nf][half * 2 + 0];
                    float g1 = acc[mf][nf][half * 2 + 1];
                    float u0 = acc[mf][nf + 4][half * 2 + 0];
                    float u1 = acc[mf][nf + 4][half * 2 + 1];
                    float h0 = g0 / (1.f + __expf(-g0)) * u0;
                    float h1 = g1 / (1.f + __expf(-g1)) * u1;
                    int col = n0 + 32 * wn + 8 * nf + 2 * q;
                    *(uint32_t*)&d_hbuf16[((size_t)e * CAPCT + m) * INTER + col] =
                        pack_h2(h0, h1);
                }
            }
        }
    }
}

// ---------------- 4) GEMM2 (fp16 smem both sides) --------------------------
// Block: M=128 x N=256, K=768. A fp16 via cp.async (d_hbuf16); B = down fp32
// LDG -> pack -> swizzled fp16 STS, reg-staged.
__global__ void __launch_bounds__(256) gemm2_mma(const float* __restrict__ down)
{
    extern __shared__ char smem[];
    const uint32_t sb = smem_u32(smem);

    int e = blockIdx.z;
    int cnt = min(d_counts[e], CAPCT);
    int m0 = blockIdx.y * 128;
    if (m0 >= cnt) return;
    int n0 = blockIdx.x * 256;
    int tid = threadIdx.x;
    int wid = tid >> 5, lane = tid & 31;
    int wm = wid >> 2, wn = wid & 3;
    int g = lane >> 2, q = lane & 3;

    const __half* aptr[2]; uint32_t sAoff[2];
#pragma unroll
    for (int j = 0; j < 2; j++) {
        int idx = tid + j * 256;
        int r = idx >> 2, o = idx & 3;
        sAoff[j] = (uint32_t)(r * 80 + o * 16);
        aptr[j] = d_hbuf16 + ((size_t)e * CAPCT + m0 + r) * INTER + o * 8;
    }
    const float* bsrc[8]; uint32_t bsts[8];
#pragma unroll
    for (int j = 0; j < 8; j++) {
        int idx = tid + j * 256;
        int r = idx >> 3, qf = (idx & 7) * 4;
        int kw = qf >> 1;
        bsts[j] = sb + BBASE + (uint32_t)((r * 16 + ((kw + 2 * r) & 15)) * 4);
        bsrc[j] = down + (size_t)e * HID * INTER + (size_t)(n0 + r) * INTER + qf;
    }

    float acc[4][8][4];
#pragma unroll
    for (int i = 0; i < 4; i++)
#pragma unroll
        for (int jn = 0; jn < 8; jn++)
#pragma unroll
            for (int c = 0; c < 4; c++) acc[i][jn][c] = 0.f;

    const int NCH = INTER / KC;  // 24
#pragma unroll
    for (int j = 0; j < 2; j++) cp16(sb + sAoff[j], aptr[j]);
    CP_COMMIT();
    float4 rB[8];
#pragma unroll
    for (int j = 0; j < 8; j++) rB[j] = *(const float4*)bsrc[j];

    for (int i = 0; i < NCH; i++) {
        int buf = i & 1;
        CP_WAIT0();
#pragma unroll
        for (int j = 0; j < 8; j++)
            sts8(bsts[j] + buf * BSTG, pack_h2(rB[j].x, rB[j].y), pack_h2(rB[j].z, rB[j].w));
        __syncthreads();
        if (i + 1 < NCH) {
            int nb = buf ^ 1;
            int k1 = (i + 1) * KC;
#pragma unroll
            for (int j = 0; j < 2; j++) cp16(sb + nb * ASTG + sAoff[j], aptr[j] + k1);
            CP_COMMIT();
#pragma unroll
            for (int j = 0; j < 8; j++) rB[j] = *(const float4*)(bsrc[j] + k1);
        }
        compute_chunk((const uint32_t*)(smem + buf * ASTG),
                      (const uint32_t*)(smem + BBASE + buf * BSTG),
                      wm, wn, g, q, acc);
    }

#pragma unroll
    for (int mf = 0; mf < 4; mf++) {
#pragma unroll
        for (int nf = 0; nf < 8; nf++) {
#pragma unroll
            for (int half = 0; half < 2; half++) {
                int m = m0 + wm * 64 + mf * 16 + g + half * 8;
                if (m < cnt) {
                    float2 yv;
                    yv.x = acc[mf][nf][half * 2 + 0];
                    yv.y = acc[mf][nf][half * 2 + 1];
                    int col = n0 + 64 * wn + 8 * nf + 2 * q;
                    *(float2*)&d_ybuf[((size_t)e * CAPCT + m) * HID + col] = yv;
                }
            }
        }
    }
}

// ---------------- 5) combine ----------------------------------------------
__global__ void __launch_bounds__(256) gather_kernel(float* __restrict__ out)
{
    int t = blockIdx.x;
    __shared__ int  sidx[TOPK];
    __shared__ float sw[TOPK];
    if (threadIdx.x < TOPK) {
        sidx[threadIdx.x] = d_sel_idx[t * TOPK + threadIdx.x];
        sw[threadIdx.x]   = d_sel_w[t * TOPK + threadIdx.x];
    }
    __syncthreads();

    const float4* yb = (const float4*)d_ybuf;
    float4* o = (float4*)(out + (size_t)t * HID);
#pragma unroll
    for (int v = threadIdx.x; v < HID / 4; v += 256) {
        float4 acc = {0.f, 0.f, 0.f, 0.f};
#pragma unroll
        for (int k = 0; k < TOPK; k++) {
            float4 yv = yb[(size_t)sidx[k] * (HID / 4) + v];
            float wk = sw[k];
            acc.x += wk * yv.x; acc.y += wk * yv.y;
            acc.z += wk * yv.z; acc.w += wk * yv.w;
        }
        o[v] = acc;
    }
}

// ---------------- launch ---------------------------------------------------
extern "C" void kernel_launch(void* const* d_in, const int* in_sizes, int n_in,
                              void* d_out, int out_size)
{
    const float* x    = (const float*)d_in[0];   // hidden_states [2,1024,2048]
    const float* gw   = (const float*)d_in[1];   // gate_weight [128,2048]
    const float* gup  = (const float*)d_in[2];   // gate_up_proj [48,1536,2048]
    const float* down = (const float*)d_in[3];   // down_proj [48,2048,768]
    const int*   o2n  = (const int*)d_in[4];     // old_to_new [128]

    cudaFuncSetAttribute(gemm1_mma, cudaFuncAttributeMaxDynamicSharedMemorySize, SMEM_BYTES);
    cudaFuncSetAttribute(gemm2_mma, cudaFuncAttributeMaxDynamicSharedMemorySize, SMEM_BYTES);

    convert_x<<<(T_TOK * HID / 4) / 256, 256>>>(x);
    gating_kernel<<<dim3(T_TOK / 32, NE_OLD / 32), 256>>>(x, gw);
    routing_kernel<<<T_TOK / 8, 256>>>(o2n);
    gemm1_mma<<<dim3(INTER / 128, CAPCT / 128, NE), 256, SMEM_BYTES>>>(gup);
    gemm2_mma<<<dim3(HID / 256, CAPCT / 128, NE), 256, SMEM_BYTES>>>(down);
    gather_kernel<<<T_TOK, 256>>>((float*)d_out);
}